// round 7
// baseline (speedup 1.0000x reference)
#include <cuda_runtime.h>
#include <cuda_bf16.h>

#define NBOX    2048
#define RKEEP   100
#define THREADS 512
#define WIN     256                  // greedy window (one warp, 8 boxes/lane)
#define NWIN    (NBOX / WIN)         // 8
#define PER_L   (WIN / 32)           // 8 boxes per lane
#define NPAIR   (NBOX / 2)
#define PAIRS_T (NPAIR / THREADS)    // 2

// One CTA per batch row. Smem ~23KB.
__global__ __launch_bounds__(THREADS)
void nms_kernel(const float* __restrict__ pred, float* __restrict__ out) {
    __shared__ unsigned long long skey[NBOX];       // 16KB, persists all phases
    __shared__ __align__(16) float4 wbox[WIN];      // 4KB window boxes (l,t,r,b)
    __shared__ float wthr[WIN];                     // exact suppression thresholds
    __shared__ unsigned char salive[WIN];           // alive after klist replay
    __shared__ __align__(16) float4 klist[RKEEP];   // kept boxes (for replay)
    __shared__ int s_slot;

    const int b   = blockIdx.x;
    const int tid = threadIdx.x;
    const float* p = pred + (size_t)b * NBOX * 5;

    // ---- Phase 1: stable descending sort of (score, index) ------------------
    // key = (score_bits<<32) | (N-1-i): scores >= 0 -> bits order-preserving;
    // descending composite == stable jnp.argsort(-scores).
    for (int i = tid; i < NBOX; i += THREADS) {
        unsigned sbits = __float_as_uint(p[i * 5 + 0]);
        skey[i] = ((unsigned long long)sbits << 32) | (unsigned)(NBOX - 1 - i);
    }
    if (tid == 0) s_slot = 0;
    __syncthreads();

    // Branchless pair-based bitonic sort (descending), unconditional SELs.
    auto substage = [&](int k, int j) {
        #pragma unroll
        for (int u = 0; u < PAIRS_T; u++) {
            int pr  = tid + u * THREADS;
            int idx = ((pr & ~(j - 1)) << 1) | (pr & (j - 1));
            int ixj = idx | j;
            unsigned long long a = skey[idx], c = skey[ixj];
            unsigned long long hi = (a > c) ? a : c;
            unsigned long long lo = (a > c) ? c : a;
            bool desc = ((idx & k) == 0);
            skey[idx] = desc ? hi : lo;
            skey[ixj] = desc ? lo : hi;
        }
    };
    for (int k = 2; k <= NBOX; k <<= 1) {
        int j = k >> 1;
        for (; j >= 64; j >>= 1) {          // cross-warp substages
            substage(k, j);
            __syncthreads();
        }
        for (; j > 0; j >>= 1) {            // warp-exclusive 64-elem blocks
            substage(k, j);
            __syncwarp();
        }
        __syncthreads();
    }

    // ---- Phase 2+3: windowed single-warp greedy NMS (exact) -----------------
    float* ob = out + (size_t)b * RKEEP * 3;
    for (int w = 0; w < NWIN; w++) {
        int slot = s_slot;                  // uniform (post-barrier)
        if (slot >= RKEEP) break;

        // Window setup by threads 0..WIN-1: gather coords, exact threshold,
        // replay already-kept boxes (no-op for window 0) -> alive flag.
        if (tid < WIN) {
            int gi   = w * WIN + tid;
            int orig = NBOX - 1 - (int)(skey[gi] & 0xFFFFFFFFu);
            const float* q = p + (size_t)orig * 5;
            float l = q[1], t = q[2], r = q[3], bo = q[4];
            float4 mb = make_float4(l, t, r, bo);
            float area = (r - l) * (bo - t);        // reference rounding
            // Exact: RN(inter/area) >= 0.5 <=> inter >= RU(area*(0.5-2^-26)).
            float thr = __double2float_ru((double)area *
                                          (0.5 - 1.4901161193847656e-8));
            unsigned char a = 1;
            for (int k2 = 0; k2 < slot; k2++) {
                float4 bi = klist[k2];
                float il = fmaxf(bi.x, mb.x), it = fmaxf(bi.y, mb.y);
                float ir = fminf(bi.z, mb.z), ib = fminf(bi.w, mb.w);
                float inter = fmaxf(0.f, ir - il) * fmaxf(0.f, ib - it);
                if (inter >= thr) a = 0;
            }
            wbox[tid] = mb; wthr[tid] = thr; salive[tid] = a;
        }
        __syncthreads();

        // Warp 0: register-resident greedy, no block barriers.
        if (tid < 32) {
            float4 mb[PER_L]; float th[PER_L];
            unsigned alive = 0;
            #pragma unroll
            for (int u = 0; u < PER_L; u++) {       // strided ownership
                int i = u * 32 + tid;               // conflict-free LDS
                mb[u] = wbox[i]; th[u] = wthr[i];
                alive |= (unsigned)(salive[i] ? 1u : 0u) << u;
            }
            while (slot < RKEEP) {
                // Min alive sorted index across warp: u ascending dominates L.
                unsigned myidx = alive ? ((__ffs(alive) - 1) * 32 + tid)
                                       : 0xFFFFu;
                unsigned idx = __reduce_min_sync(0xFFFFFFFFu, myidx);
                if (idx == 0xFFFFu) break;          // window exhausted

                float4 bi = wbox[idx];              // broadcast LDS.128
                if (tid == 0) {                     // vals = (top,right,bottom)
                    ob[slot * 3 + 0] = bi.y;
                    ob[slot * 3 + 1] = bi.z;
                    ob[slot * 3 + 2] = bi.w;
                    klist[slot] = bi;
                }
                slot++;

                // 8 IoUs in registers; self-IoU clears the candidate's bit
                // (inter(i,i) = area >= thr ~ 0.5*area, area > 0 always).
                #pragma unroll
                for (int u = 0; u < PER_L; u++) {
                    float il = fmaxf(bi.x, mb[u].x), it = fmaxf(bi.y, mb[u].y);
                    float ir = fminf(bi.z, mb[u].z), ib = fminf(bi.w, mb[u].w);
                    float inter = fmaxf(0.f, ir - il) * fmaxf(0.f, ib - it);
                    if (inter >= th[u]) alive &= ~(1u << u);
                }
            }
            if (tid == 0) s_slot = slot;
        }
        __syncthreads();                    // publish s_slot + klist
    }

    // Zero-fill unused output slots (out is poisoned by the harness).
    int fslot = s_slot;
    for (int k2 = fslot * 3 + tid; k2 < RKEEP * 3; k2 += THREADS) ob[k2] = 0.f;
}

extern "C" void kernel_launch(void* const* d_in, const int* in_sizes, int n_in,
                              void* d_out, int out_size) {
    const float* pred = (const float*)d_in[0];   // [32, 2048, 5] f32
    float* out = (float*)d_out;                  // [32, 100, 3] f32
    (void)in_sizes; (void)n_in; (void)out_size;
    nms_kernel<<<32, THREADS>>>(pred, out);
}